// round 17
// baseline (speedup 1.0000x reference)
#include <cuda_runtime.h>
#include <math.h>
#include <stdint.h>

constexpr int B_    = 512;
constexpr int LEN_  = 1000;
constexpr int D_    = 16;
constexpr int HID_  = 256;
constexpr int WIN_  = 64;
constexpr int PAIRS_  = 120;
constexpr int LOGSIG_ = 136;
constexpr int K1_   = HID_ + LOGSIG_;   // 392
constexpr int K1P_  = 416;              // 13*32
constexpr int BT_   = 16;               // rows per CTA (parallel phase)
constexpr int NCH_  = 32;               // cumsum time chunks
constexpr int WTS_  = 256 * 32;         // swizzled W tile (floats), parallel

__device__ float g_X[(size_t)B_ * LEN_ * D_];
__device__ float g_ls[(size_t)WIN_ * B_ * LOGSIG_];
__device__ float g_lastall[24][(size_t)B_ * HID_];
__device__ float g_h1[(size_t)B_ * HID_];
__device__ float g_h2[(size_t)B_ * HID_];
__device__ float g_part[(size_t)B_ * NCH_ * D_];
__device__ float g_dts[LEN_ - 1];
__device__ int   g_tidx[WIN_ - 1];
__device__ int   g_sidx[WIN_ - 1];
__device__ int   g_seg[WIN_];
__device__ int   g_updflag[WIN_];
__device__ int   g_iu[PAIRS_];
__device__ int   g_ju[PAIRS_];

__host__ __device__ __forceinline__ double tb_d(int i) {
    return (i == LEN_ - 1) ? 1.0 : (double)i * (1.0 / 999.0);
}
__host__ __device__ __forceinline__ double tt_d(int k) {
    return (k == WIN_ - 1) ? 1.0 : (double)k * (1.0 / 63.0);
}

__host__ __device__ inline void compute_upd(bool upd[WIN_]) {
    double tu[20];
    for (int j = 0; j < 20; j++) tu[j] = tb_d(50 * j);
    int u_idx[63];
    for (int k = 1; k < 64; k++) {
        double t = tt_d(k);
        int uj = 0;
        for (int j = 0; j < 20; j++) if (tu[j] <= t) uj = j;
        u_idx[k - 1] = uj;
    }
    double qt[64]; int qn = 0, last = -1;
    for (int k = 0; k < 63; k++) {
        int iu = u_idx[k] < 0 ? 0 : u_idx[k];
        if (iu != last) { qt[qn++] = tu[iu]; last = iu; }
    }
    qt[qn++] = tt_d(63);
    int qh = 0;
    for (int i = 0; i < 64; i++) {
        upd[i] = false;
        if (qh < qn && tt_d(i) >= qt[qh]) { qh++; upd[i] = true; }
    }
}

__global__ void sched_kernel() {
    int tid = threadIdx.x;
    for (int i = tid; i < LEN_ - 1; i += blockDim.x)
        g_dts[i] = sqrtf((float)(tb_d(i + 1) - tb_d(i)));
    if (tid < WIN_ - 1) {
        double t = tt_d(tid + 1);
        int ti = 0;
        for (int i = 0; i < LEN_; i++) if (tb_d(i) <= t) ti = i;
        g_tidx[tid] = ti;
        int uj = 0;
        for (int j = 0; j < LEN_ / 50; j++) if (tb_d(50 * j) <= t) uj = j;
        g_sidx[tid] = 50 * uj;
    }
    if (tid >= 64 && tid < 64 + PAIRS_) {
        int p = tid - 64;
        int i = 0, accp = 0;
        while (accp + (D_ - 1 - i) <= p) { accp += D_ - 1 - i; i++; }
        g_iu[p] = i;
        g_ju[p] = i + 1 + (p - accp);
    }
    if (tid == 0) {
        bool upd[WIN_];
        compute_upd(upd);
        int s = 0;
        for (int i = 0; i < WIN_; i++) {
            g_seg[i] = s;
            g_updflag[i] = upd[i] ? 1 : 0;
            if (upd[i]) s++;
        }
    }
}

__global__ void zero_last_kernel() {
    int g = blockIdx.x * blockDim.x + threadIdx.x;
    if (g < B_ * HID_) g_lastall[0][g] = 0.f;
}

__device__ __forceinline__ void chunk_rng(int c, int& t0, int& t1) {
    t0 = (c * 999) / NCH_ + 1;
    t1 = ((c + 1) * 999) / NCH_;
}

__global__ void cumsum_part_kernel(const float* __restrict__ z) {
    int g = blockIdx.x * blockDim.x + threadIdx.x;
    int d4 = g & 3, c = (g >> 2) & (NCH_ - 1), b = g >> 7;
    int t0, t1; chunk_rng(c, t0, t1);
    const float4* zp = reinterpret_cast<const float4*>(z + (size_t)b * LEN_ * D_) + d4;
    float4 s = make_float4(0.f, 0.f, 0.f, 0.f);
    for (int t = t0; t <= t1; t++) {
        float dt = g_dts[t - 1];
        float4 zv = zp[t * 4];
        s.x += zv.x * dt; s.y += zv.y * dt; s.z += zv.z * dt; s.w += zv.w * dt;
    }
    reinterpret_cast<float4*>(g_part + ((size_t)b * NCH_ + c) * D_)[d4] = s;
}

__global__ void cumsum_write_kernel(const float* __restrict__ z) {
    int g = blockIdx.x * blockDim.x + threadIdx.x;
    int d4 = g & 3, c = (g >> 2) & (NCH_ - 1), b = g >> 7;
    float4 acc = make_float4(0.f, 0.f, 0.f, 0.f);
    for (int cc = 0; cc < c; cc++) {
        float4 p = reinterpret_cast<const float4*>(g_part + ((size_t)b * NCH_ + cc) * D_)[d4];
        acc.x += p.x; acc.y += p.y; acc.z += p.z; acc.w += p.w;
    }
    int t0, t1; chunk_rng(c, t0, t1);
    const float4* zp = reinterpret_cast<const float4*>(z + (size_t)b * LEN_ * D_) + d4;
    float4* xp = reinterpret_cast<float4*>(g_X + (size_t)b * LEN_ * D_) + d4;
    if (c == 0) xp[0] = make_float4(0.f, 0.f, 0.f, 0.f);
    for (int t = t0; t <= t1; t++) {
        float dt = g_dts[t - 1];
        float4 zv = zp[t * 4];
        acc.x += zv.x * dt; acc.y += zv.y * dt; acc.z += zv.z * dt; acc.w += zv.w * dt;
        xp[t * 4] = acc;
    }
}

__global__ void logsig_kernel() {
    int kk = blockIdx.x, b = blockIdx.y, tid = threadIdx.x;
    if (kk == 0) {
        if (tid < LOGSIG_) g_ls[(size_t)b * LOGSIG_ + tid] = 0.f;
        return;
    }
    int k = kk - 1, t1 = g_tidx[k], s0 = g_sidx[k];
    int nrow = t1 - s0 + 1;                          // <= 50
    __shared__ float sX[50 * 16];
    const float* xb = g_X + ((size_t)b * LEN_ + s0) * D_;
    for (int e = tid; e < (nrow * D_) >> 2; e += blockDim.x)
        reinterpret_cast<float4*>(sX)[e] = reinterpret_cast<const float4*>(xb)[e];
    __syncthreads();
    float* outp = g_ls + ((size_t)kk * B_ + b) * LOGSIG_;
    if (tid < D_) {
        outp[tid] = sX[(t1 - s0) * D_ + tid];
    } else if (tid < LOGSIG_) {
        int p = tid - D_, iu = g_iu[p], ju = g_ju[p];
        float xi = sX[iu], xj = sX[ju];
        float acc = 0.f;
        for (int s = 1; s < nrow; s++) {
            float yi = sX[s * D_ + iu], yj = sX[s * D_ + ju];
            acc += xi * (yj - xj) - xj * (yi - xi);
            xi = yi; xj = yj;
        }
        outp[tid] = 0.5f * acc;
    }
}

__device__ __forceinline__ void ffma2(unsigned long long& acc,
                                      unsigned long long a, unsigned long long b) {
    asm("fma.rn.f32x2 %0, %1, %2, %0;" : "+l"(acc) : "l"(a), "l"(b));
}

// ============ PARALLEL PHASE (unchanged from R12) ============

__device__ __forceinline__ void stage_sw256(const float* __restrict__ Wg, int Ktrue,
                                            int k0, float* sWbuf, int tid) {
    #pragma unroll
    for (int u = 0; u < 8; u++) {
        int g = (u << 8) + tid;
        int row = g >> 3;
        int c4  = g & 7;
        int k   = k0 + (c4 << 2);
        uint32_t dst = (uint32_t)__cvta_generic_to_shared(
            sWbuf + row * 32 + ((c4 ^ (row & 7)) << 2));
        bool valid = (k + 4 <= Ktrue);
        const float* src = valid ? (Wg + (size_t)row * Ktrue + k) : Wg;
        int sz = valid ? 16 : 0;
        asm volatile("cp.async.cg.shared.global [%0], [%1], 16, %2;"
                     :: "r"(dst), "l"(src), "r"(sz));
    }
    asm volatile("cp.async.commit_group;");
}

__device__ __forceinline__ void gemm44(
    const float* __restrict__ Wg, int Ktrue, int nch,
    const float* __restrict__ sin, int sstride,
    float* __restrict__ sW, int tid, float outv[4][4])
{
    const int jt = tid & 63;
    const int rg = tid >> 6;
    const int lane = tid & 31;

    unsigned long long acc[4][4];
    #pragma unroll
    for (int q = 0; q < 4; q++)
        #pragma unroll
        for (int r = 0; r < 4; r++) acc[q][r] = 0ULL;

    stage_sw256(Wg, Ktrue, 0, sW, tid);
    for (int ch = 0; ch < nch; ch++) {
        if (ch + 1 < nch) {
            stage_sw256(Wg, Ktrue, (ch + 1) << 5, sW + ((ch + 1) & 1) * WTS_, tid);
            asm volatile("cp.async.wait_group 1;");
        } else {
            asm volatile("cp.async.wait_group 0;");
        }
        __syncthreads();
        const float* cur = sW + (ch & 1) * WTS_;
        const int k0 = ch << 5;

        ulonglong2 xs = *reinterpret_cast<const ulonglong2*>(
            sin + (rg * 4 + (lane >> 3)) * sstride + k0 + ((lane & 7) << 2));

        #pragma unroll
        for (int c4 = 0; c4 < 8; c4++) {
            ulonglong2 wv[4];
            #pragma unroll
            for (int q = 0; q < 4; q++) {
                int row = jt + (q << 6);
                wv[q] = *reinterpret_cast<const ulonglong2*>(
                    cur + row * 32 + ((c4 ^ (row & 7)) << 2));
            }
            #pragma unroll
            for (int rr = 0; rr < 4; rr++) {
                const int src = (rr << 3) + c4;
                unsigned long long xa = __shfl_sync(0xffffffffu, xs.x, src);
                unsigned long long xb = __shfl_sync(0xffffffffu, xs.y, src);
                #pragma unroll
                for (int q = 0; q < 4; q++) {
                    ffma2(acc[q][rr], wv[q].x, xa);
                    ffma2(acc[q][rr], wv[q].y, xb);
                }
            }
        }
        __syncthreads();
    }
    #pragma unroll
    for (int q = 0; q < 4; q++)
        #pragma unroll
        for (int r = 0; r < 4; r++) {
            float lo = __uint_as_float((unsigned)acc[q][r]);
            float hi = __uint_as_float((unsigned)(acc[q][r] >> 32));
            outv[q][r] = lo + hi;
        }
}

__global__ void __launch_bounds__(256, 2)
rnn_all_kernel(const float* __restrict__ W1, const float* __restrict__ b1,
               const float* __restrict__ W2, const float* __restrict__ b2,
               const float* __restrict__ W3, const float* __restrict__ b3,
               const float* __restrict__ Wl, float* __restrict__ out)
{
    extern __shared__ float smem[];
    float* sW = smem;                       // 2 * 256*32 swizzled
    float* R0 = sW + 2 * WTS_;              // 16*416
    float* R1 = R0 + BT_ * K1P_;            // 16*256

    const int tid  = threadIdx.x;
    const int jt   = tid & 63;
    const int rg   = tid >> 6;
    const int step = blockIdx.x >> 5;       // 32 CTAs per step
    const int b0   = (blockIdx.x & 31) * BT_;

    float v[4][4];

    if (g_updflag[step]) {
        const float* hsrc = g_lastall[g_seg[step] + 1];
        for (int r = 0; r < BT_; r++) {
            int b = b0 + r;
            for (int c = tid; c < HID_; c += 256)
                R1[r * HID_ + c] = hsrc[(size_t)b * HID_ + c];
        }
    } else {
        const float* last_in = g_lastall[g_seg[step]];
        for (int r = 0; r < BT_; r++) {
            int b = b0 + r;
            for (int c = tid; c < K1P_; c += 256) {
                float vv = 0.f;
                if (c < HID_)     vv = last_in[(size_t)b * HID_ + c];
                else if (c < K1_) vv = g_ls[((size_t)step * B_ + b) * LOGSIG_ + (c - HID_)];
                R0[r * K1P_ + c] = vv;
            }
        }

        gemm44(W1, K1_, K1P_ / 32, R0, K1P_, sW, tid, v);
        #pragma unroll
        for (int q = 0; q < 4; q++) {
            int j = jt + (q << 6); float bb = b1[j];
            #pragma unroll
            for (int rr = 0; rr < 4; rr++)
                R1[(rg * 4 + rr) * HID_ + j] = fmaxf(v[q][rr] + bb, 0.f);
        }
        __syncthreads();

        gemm44(W2, HID_, HID_ / 32, R1, HID_, sW, tid, v);
        __syncthreads();
        #pragma unroll
        for (int q = 0; q < 4; q++) {
            int j = jt + (q << 6); float bb = b2[j];
            #pragma unroll
            for (int rr = 0; rr < 4; rr++)
                R0[(rg * 4 + rr) * HID_ + j] = fmaxf(v[q][rr] + bb, 0.f);
        }
        __syncthreads();

        gemm44(W3, HID_, HID_ / 32, R0, HID_, sW, tid, v);
        __syncthreads();
        #pragma unroll
        for (int q = 0; q < 4; q++) {
            int j = jt + (q << 6); float bb = b3[j];
            #pragma unroll
            for (int rr = 0; rr < 4; rr++)
                R1[(rg * 4 + rr) * HID_ + j] = tanhf(v[q][rr] + bb);
        }
        __syncthreads();
    }

    gemm44(Wl, HID_, HID_ / 32, R1, HID_, sW, tid, v);
    #pragma unroll
    for (int q = 0; q < 4; q++) {
        int j = jt + (q << 6);
        #pragma unroll
        for (int rr = 0; rr < 4; rr++) {
            int b = b0 + rg * 4 + rr;
            out[((size_t)b * WIN_ + step) * HID_ + j] = v[q][rr];
        }
    }
}

// ============ SERIAL PHASE: per-layer wide launches ============
// grid = 128 CTAs = (4 j-blocks of 64) x (32 row-blocks of 16), 256 threads.
// thread = 1 j x 4 rows. W chunk (64x32) lane-distinct once/warp; x broadcast.

__device__ __forceinline__ void stage_w64(const float* __restrict__ Wg, int Ktrue,
                                          int jb, int k0, float* buf, int tid) {
    #pragma unroll
    for (int u = 0; u < 2; u++) {
        int g = (u << 8) + tid;          // 512 float4s
        int row = g >> 3;
        int c4  = g & 7;
        int k   = k0 + (c4 << 2);
        uint32_t d = (uint32_t)__cvta_generic_to_shared(
            buf + row * 32 + ((c4 ^ (row & 7)) << 2));
        bool valid = (k + 4 <= Ktrue);
        const float* src = valid ? (Wg + (size_t)((jb << 6) + row) * Ktrue + k) : Wg;
        int sz = valid ? 16 : 0;
        asm volatile("cp.async.cg.shared.global [%0], [%1], 16, %2;"
                     :: "r"(d), "l"(src), "r"(sz));
    }
    asm volatile("cp.async.commit_group;");
}

__global__ void __launch_bounds__(256, 2)
serial_layer_kernel(const float* __restrict__ Wg, const float* __restrict__ bias,
                    int Ktrue, int nch, int KP,
                    int in_mode, int si, int step, int act_tanh, int out_mode)
{
    extern __shared__ float smem[];
    float* sW = smem;              // 2 x (64 x 32)
    float* sX = sW + 2 * 2048;     // 16 x KP

    const int tid = threadIdx.x;
    const int jt  = tid & 63;
    const int rg  = tid >> 6;      // 0..3 -> rows rg*4 .. rg*4+3
    const int jb  = blockIdx.x & 3;
    const int rb  = blockIdx.x >> 2;   // 0..31
    const int j   = (jb << 6) + jt;
    const int row0 = rb << 4;          // 16 rows per CTA

    // stage x (16 rows x KP)
    const float* lastp = g_lastall[si];
    for (int r = 0; r < 16; r++) {
        int b = row0 + r;
        for (int c = tid; c < KP; c += 256) {
            float v;
            if (in_mode == 0) {
                v = 0.f;
                if (c < HID_)      v = lastp[(size_t)b * HID_ + c];
                else if (c < K1_)  v = g_ls[((size_t)step * B_ + b) * LOGSIG_ + (c - HID_)];
            } else if (in_mode == 1) {
                v = g_h1[(size_t)b * HID_ + c];
            } else {
                v = g_h2[(size_t)b * HID_ + c];
            }
            sX[r * KP + c] = v;
        }
    }

    unsigned long long acc[4] = {0ULL, 0ULL, 0ULL, 0ULL};

    stage_w64(Wg, Ktrue, jb, 0, sW, tid);
    for (int ch = 0; ch < nch; ch++) {
        if (ch + 1 < nch) {
            stage_w64(Wg, Ktrue, jb, (ch + 1) << 5, sW + ((ch + 1) & 1) * 2048, tid);
            asm volatile("cp.async.wait_group 1;");
        } else {
            asm volatile("cp.async.wait_group 0;");
        }
        __syncthreads();     // also orders sX writes before first reads
        const float* cur = sW + (ch & 1) * 2048;
        const int k0 = ch << 5;

        #pragma unroll
        for (int c4 = 0; c4 < 8; c4++) {
            ulonglong2 w2 = *reinterpret_cast<const ulonglong2*>(
                cur + jt * 32 + ((c4 ^ (jt & 7)) << 2));
            #pragma unroll
            for (int rr = 0; rr < 4; rr++) {
                ulonglong2 x2 = *reinterpret_cast<const ulonglong2*>(
                    sX + (rg * 4 + rr) * KP + k0 + (c4 << 2));   // warp-broadcast
                ffma2(acc[rr], w2.x, x2.x);
                ffma2(acc[rr], w2.y, x2.y);
            }
        }
        __syncthreads();
    }

    float bb = bias[j];
    float* dstp = (out_mode == 0) ? g_h1
                : (out_mode == 1) ? g_h2
                : g_lastall[si + 1];
    #pragma unroll
    for (int rr = 0; rr < 4; rr++) {
        float lo = __uint_as_float((unsigned)acc[rr]);
        float hi = __uint_as_float((unsigned)(acc[rr] >> 32));
        float v = lo + hi + bb;
        v = act_tanh ? tanhf(v) : fmaxf(v, 0.f);
        dstp[(size_t)(row0 + (rg << 2) + rr) * HID_ + j] = v;
    }
}

extern "C" void kernel_launch(void* const* d_in, const int* in_sizes, int n_in,
                              void* d_out, int out_size) {
    (void)in_sizes; (void)n_in; (void)out_size;
    const float* z  = (const float*)d_in[0];
    const float* W1 = (const float*)d_in[1];
    const float* b1 = (const float*)d_in[2];
    const float* W2 = (const float*)d_in[3];
    const float* b2 = (const float*)d_in[4];
    const float* W3 = (const float*)d_in[5];
    const float* b3 = (const float*)d_in[6];
    const float* Wl = (const float*)d_in[7];
    float* out = (float*)d_out;

    const size_t smem_par =
        (2 * WTS_ + BT_ * K1P_ + BT_ * HID_) * sizeof(float);     // ~108 KB
    cudaFuncSetAttribute(rnn_all_kernel,
                         cudaFuncAttributeMaxDynamicSharedMemorySize, (int)smem_par);

    const size_t smem_s1 = (2 * 2048 + 16 * K1P_) * sizeof(float);  // 43008 B
    const size_t smem_s2 = (2 * 2048 + 16 * HID_) * sizeof(float);  // 32768 B

    sched_kernel<<<1, 256>>>();
    zero_last_kernel<<<(B_ * HID_ + 255) / 256, 256>>>();
    cumsum_part_kernel<<<(B_ * NCH_ * 4) / 256, 256>>>(z);
    cumsum_write_kernel<<<(B_ * NCH_ * 4) / 256, 256>>>(z);
    logsig_kernel<<<dim3(WIN_, B_), 160>>>();

    bool upd[WIN_];
    compute_upd(upd);
    int si = 0;
    for (int i = 0; i < WIN_; i++) {
        if (!upd[i]) continue;
        serial_layer_kernel<<<128, 256, smem_s1>>>(
            W1, b1, K1_, K1P_ / 32, K1P_, 0, si, i, 0, 0);
        serial_layer_kernel<<<128, 256, smem_s2>>>(
            W2, b2, HID_, HID_ / 32, HID_, 1, si, i, 0, 1);
        serial_layer_kernel<<<128, 256, smem_s2>>>(
            W3, b3, HID_, HID_ / 32, HID_, 2, si, i, 1, 2);
        si++;
    }

    rnn_all_kernel<<<WIN_ * (B_ / BT_), 256, smem_par>>>(
        W1, b1, W2, b2, W3, b3, Wl, out);
}